// round 10
// baseline (speedup 1.0000x reference)
#include <cuda_runtime.h>

#define N_   16
#define C_   512
#define H_   64
#define W_   64
#define GRP  4
#define CG   128
#define MIP  16
#define EPS_ 1e-5f

// Scratch (allocation-free): pooled rows/cols and gate vectors.
__device__ float g_gh[N_ * C_ * H_];   // [n][ch][h]  mean over w
__device__ float g_gw[N_ * C_ * W_];   // [n][ch][w]  mean over h
__device__ float g_ah[N_ * C_ * H_];   // sigmoid gate along h
__device__ float g_aw[N_ * C_ * W_];   // sigmoid gate along w

// ---------------------------------------------------------------------------
// Kernel 1: shuffle-based pool (R9 proven: 25.3us, 5.5TB/s).
// ---------------------------------------------------------------------------
__global__ __launch_bounds__(256) void pool_kernel(const float* __restrict__ x) {
    __shared__ float scol[16 * 64];     // [sub][w] partial col sums
    const int img = blockIdx.x;         // n*512 + ch
    const float4* __restrict__ xp = (const float4*)(x + (size_t)img * 4096);
    const int tid = threadIdx.x;
    const int sub = tid >> 4;           // 0..15
    const int w4  = tid & 15;           // w-quad index (fixed over k)

    float4 v0 = xp[tid];
    float4 v1 = xp[256 + tid];
    float4 v2 = xp[512 + tid];
    float4 v3 = xp[768 + tid];

    float4 ac;
    ac.x = v0.x + v1.x + v2.x + v3.x;
    ac.y = v0.y + v1.y + v2.y + v3.y;
    ac.z = v0.z + v1.z + v2.z + v3.z;
    ac.w = v0.w + v1.w + v2.w + v3.w;
    *(float4*)&scol[sub * 64 + w4 * 4] = ac;

    float r0 = (v0.x + v0.y) + (v0.z + v0.w);
    float r1 = (v1.x + v1.y) + (v1.z + v1.w);
    float r2 = (v2.x + v2.y) + (v2.z + v2.w);
    float r3 = (v3.x + v3.y) + (v3.z + v3.w);
#pragma unroll
    for (int d = 1; d < 16; d <<= 1) {
        r0 += __shfl_xor_sync(0xffffffffu, r0, d);
        r1 += __shfl_xor_sync(0xffffffffu, r1, d);
        r2 += __shfl_xor_sync(0xffffffffu, r2, d);
        r3 += __shfl_xor_sync(0xffffffffu, r3, d);
    }
    if (w4 == 0) g_gh[img * 64 + sub]      = r0 * (1.f / 64.f);
    if (w4 == 1) g_gh[img * 64 + 16 + sub] = r1 * (1.f / 64.f);
    if (w4 == 2) g_gh[img * 64 + 32 + sub] = r2 * (1.f / 64.f);
    if (w4 == 3) g_gh[img * 64 + 48 + sub] = r3 * (1.f / 64.f);

    __syncthreads();

    if (tid < 64) {
        float s0 = 0.f, s1 = 0.f;
#pragma unroll
        for (int s = 0; s < 16; s += 2) {
            s0 += scol[s * 64 + tid];
            s1 += scol[(s + 1) * 64 + tid];
        }
        g_gw[img * 64 + tid] = (s0 + s1) * (1.f / 64.f);
    }
}

// ---------------------------------------------------------------------------
// Kernel 2: per-(n,g) tiny MLP + BN + hard-swish + two sigmoid gate GEMMs.
// ---------------------------------------------------------------------------
__global__ __launch_bounds__(128) void mlp_kernel(
    const float* __restrict__ W1, const float* __restrict__ b1,
    const float* __restrict__ gamma, const float* __restrict__ beta,
    const float* __restrict__ mean_, const float* __restrict__ var_,
    const float* __restrict__ Wh, const float* __restrict__ bh,
    const float* __restrict__ Ww, const float* __restrict__ bw)
{
    __shared__ float W1s[MIP * CG];   // [m][c]
    __shared__ float ys[MIP * 128];   // [m][l]  post-activation
    __shared__ float Whs[CG * MIP];   // [c][m]
    __shared__ float Wws[CG * MIP];   // [c][m]
    __shared__ float bhs[CG], bws[CG];
    __shared__ float scale_s[MIP], shift_s[MIP], b1s[MIP];

    const int tid = threadIdx.x;          // 0..127
    const int blk = blockIdx.x;           // n*4 + g
    const int n = blk >> 2, g = blk & 3;

    for (int i = tid; i < MIP * CG; i += 128) {
        W1s[i] = W1[i];
        Whs[i] = Wh[i];
        Wws[i] = Ww[i];
    }
    bhs[tid] = bh[tid];
    bws[tid] = bw[tid];
    if (tid < MIP) {
        float sc = gamma[tid] * rsqrtf(var_[tid] + EPS_);
        scale_s[tid] = sc;
        shift_s[tid] = beta[tid] - mean_[tid] * sc;
        b1s[tid] = b1[tid];
    }
    __syncthreads();

    const int l = tid;
    const float* __restrict__ src = (l < 64)
        ? &g_gh[((size_t)n * C_ + g * CG) * 64 + l]
        : &g_gw[((size_t)n * C_ + g * CG) * 64 + (l - 64)];

    float acc[MIP];
#pragma unroll
    for (int m = 0; m < MIP; m++) acc[m] = 0.f;

#pragma unroll 4
    for (int c = 0; c < CG; c++) {
        float yc = src[c * 64];
#pragma unroll
        for (int m = 0; m < MIP; m++) acc[m] += W1s[m * CG + c] * yc;
    }

#pragma unroll
    for (int m = 0; m < MIP; m++) {
        float v = acc[m] + b1s[m];
        v = v * scale_s[m] + shift_s[m];
        float r = fminf(fmaxf(v + 3.f, 0.f), 6.f);
        ys[m * 128 + l] = v * r * (1.f / 6.f);
    }
    __syncthreads();

    const int c = tid;
    float whr[MIP], wwr[MIP];
#pragma unroll
    for (int m = 0; m < MIP; m++) {
        whr[m] = Whs[c * MIP + m];
        wwr[m] = Wws[c * MIP + m];
    }
    const float bhc = bhs[c], bwc = bws[c];
    const int ch = g * CG + c;
    float* __restrict__ ah_out = &g_ah[((size_t)n * C_ + ch) * 64];
    float* __restrict__ aw_out = &g_aw[((size_t)n * C_ + ch) * 64];

#pragma unroll 2
    for (int l2 = 0; l2 < 64; l2++) {
        float sh = bhc, sw2 = bwc;
#pragma unroll
        for (int m = 0; m < MIP; m++) {
            sh  += whr[m] * ys[m * 128 + l2];
            sw2 += wwr[m] * ys[m * 128 + l2 + 64];
        }
        ah_out[l2] = 1.f / (1.f + __expf(-sh));
        aw_out[l2] = 1.f / (1.f + __expf(-sw2));
    }
}

// ---------------------------------------------------------------------------
// Kernel 3: apply, 4 tiles/CTA, FULL unroll so tile index t=k>>2 is
// compile-time (R7's spill bug fixed), 16 front-batched float4 loads,
// reversed traversal, one barrier.
// ---------------------------------------------------------------------------
__global__ __launch_bounds__(256) void apply_kernel(const float* __restrict__ x,
                                                    float* __restrict__ out) {
    __shared__ float sAH[4 * 64];
    __shared__ float sAW[4 * 64];

    const int tid  = threadIdx.x;
    const int blkR = (N_ * C_ / 4 - 1) - blockIdx.x;   // reversed traversal
    const int img0 = blkR * 4;                          // 4 consecutive imgs
    const int n    = img0 >> 9;
    const int ch0  = img0 & 511;

    // stage gates for 4 tiles (contiguous): 256 floats each, coalesced
    sAH[tid] = g_ah[(size_t)img0 * 64 + tid];
    sAW[tid] = g_aw[(size_t)img0 * 64 + tid];

    const float4* __restrict__ xp = (const float4*)(x + (size_t)img0 * 4096);

    // front-batch all 16 loads (independent of the gate loads)
    float4 v[16];
#pragma unroll
    for (int k = 0; k < 16; k++) v[k] = xp[k * 256 + tid];

    // output pointers (compile-time indexed below)
    float4* op0; float4* op1; float4* op2; float4* op3;
    {
        int c0 = ch0;
        op0 = (float4*)(out + ((size_t)n * 512 + ((c0 & 3) * 128 + (c0 >> 2))) * 4096);
        int c1 = ch0 + 1;
        op1 = (float4*)(out + ((size_t)n * 512 + ((c1 & 3) * 128 + (c1 >> 2))) * 4096);
        int c2 = ch0 + 2;
        op2 = (float4*)(out + ((size_t)n * 512 + ((c2 & 3) * 128 + (c2 >> 2))) * 4096);
        int c3 = ch0 + 3;
        op3 = (float4*)(out + ((size_t)n * 512 + ((c3 & 3) * 128 + (c3 >> 2))) * 4096);
    }

    __syncthreads();

#pragma unroll
    for (int k = 0; k < 16; k++) {
        const int t      = k >> 2;                 // compile-time tile index
        const int within = (k & 3) * 256 + tid;    // float4 index inside tile
        const int h      = within >> 4;
        const int w      = (within & 15) << 2;
        const float a = sAH[t * 64 + h];
        const float* aw = &sAW[t * 64 + w];
        float4 r = v[k];
        r.x *= a * aw[0];
        r.y *= a * aw[1];
        r.z *= a * aw[2];
        r.w *= a * aw[3];
        float4* op = (t == 0) ? op0 : (t == 1) ? op1 : (t == 2) ? op2 : op3;
        op[within] = r;
    }
}

extern "C" void kernel_launch(void* const* d_in, const int* in_sizes, int n_in,
                              void* d_out, int out_size) {
    const float* x     = (const float*)d_in[0];
    const float* W1    = (const float*)d_in[1];
    const float* b1    = (const float*)d_in[2];
    const float* gamma = (const float*)d_in[3];
    const float* beta  = (const float*)d_in[4];
    const float* mean_ = (const float*)d_in[5];
    const float* var_  = (const float*)d_in[6];
    const float* Wh    = (const float*)d_in[7];
    const float* bh    = (const float*)d_in[8];
    const float* Ww    = (const float*)d_in[9];
    const float* bw    = (const float*)d_in[10];
    float* out = (float*)d_out;

    pool_kernel<<<N_ * C_, 256>>>(x);
    mlp_kernel<<<N_ * GRP, 128>>>(W1, b1, gamma, beta, mean_, var_, Wh, bh, Ww, bw);
    apply_kernel<<<(N_ * C_) / 4, 256>>>(x, out);
}

// round 11
// speedup vs baseline: 1.0423x; 1.0423x over previous
#include <cuda_runtime.h>

#define N_   16
#define C_   512
#define GRP  4
#define CG   128
#define MIP  16
#define EPS_ 1e-5f

// Scratch (allocation-free).
__device__ float g_gh[N_ * C_ * 64];   // [n][ch][h]
__device__ float g_gw[N_ * C_ * 64];   // [n][ch][w]
__device__ float g_ah[N_ * C_ * 64];
__device__ float g_aw[N_ * C_ * 64];

// ---------------------------------------------------------------------------
// Kernel 1: shuffle pool, 2 images per CTA (8 front-batched float4 loads).
// ---------------------------------------------------------------------------
__global__ __launch_bounds__(256) void pool_kernel(const float* __restrict__ x) {
    __shared__ float scol[2][16 * 64];
    const int img0 = blockIdx.x * 2;
    const float4* __restrict__ xp = (const float4*)(x + (size_t)img0 * 4096);
    const int tid = threadIdx.x;
    const int sub = tid >> 4;           // 0..15
    const int w4  = tid & 15;           // w-quad (k-invariant)

    float4 v[8];
#pragma unroll
    for (int k = 0; k < 8; k++) v[k] = xp[k * 256 + tid];

    // col partials per image
    float4 acA, acB;
    acA.x = v[0].x + v[1].x + v[2].x + v[3].x;
    acA.y = v[0].y + v[1].y + v[2].y + v[3].y;
    acA.z = v[0].z + v[1].z + v[2].z + v[3].z;
    acA.w = v[0].w + v[1].w + v[2].w + v[3].w;
    acB.x = v[4].x + v[5].x + v[6].x + v[7].x;
    acB.y = v[4].y + v[5].y + v[6].y + v[7].y;
    acB.z = v[4].z + v[5].z + v[6].z + v[7].z;
    acB.w = v[4].w + v[5].w + v[6].w + v[7].w;
    *(float4*)&scol[0][sub * 64 + w4 * 4] = acA;
    *(float4*)&scol[1][sub * 64 + w4 * 4] = acB;

    // row sums: butterfly over 16-lane groups
    float r[8];
#pragma unroll
    for (int k = 0; k < 8; k++)
        r[k] = (v[k].x + v[k].y) + (v[k].z + v[k].w);
#pragma unroll
    for (int d = 1; d < 16; d <<= 1) {
#pragma unroll
        for (int k = 0; k < 8; k++)
            r[k] += __shfl_xor_sync(0xffffffffu, r[k], d);
    }
    if (w4 < 8) {
        int im  = (w4 >> 2);              // 0 or 1
        int k16 = (w4 & 3);               // row block
        g_gh[(size_t)(img0 + im) * 64 + k16 * 16 + sub] = r[w4] * (1.f / 64.f);
    }
    __syncthreads();

    // col finalize: 128 threads, 64 per image
    if (tid < 128) {
        int im = tid >> 6, w = tid & 63;
        float s0 = 0.f, s1 = 0.f;
#pragma unroll
        for (int s = 0; s < 16; s += 2) {
            s0 += scol[im][s * 64 + w];
            s1 += scol[im][(s + 1) * 64 + w];
        }
        g_gw[(size_t)(img0 + im) * 64 + w] = (s0 + s1) * (1.f / 64.f);
    }
}

// ---------------------------------------------------------------------------
// Kernel 2: tiny MLP + gates. PDL: weight loads precede the grid sync.
// ---------------------------------------------------------------------------
__global__ __launch_bounds__(128) void mlp_kernel(
    const float* __restrict__ W1, const float* __restrict__ b1,
    const float* __restrict__ gamma, const float* __restrict__ beta,
    const float* __restrict__ mean_, const float* __restrict__ var_,
    const float* __restrict__ Wh, const float* __restrict__ bh,
    const float* __restrict__ Ww, const float* __restrict__ bw)
{
    __shared__ float W1s[MIP * CG];
    __shared__ float ys[MIP * 128];
    __shared__ float Whs[CG * MIP];
    __shared__ float Wws[CG * MIP];
    __shared__ float bhs[CG], bws[CG];
    __shared__ float scale_s[MIP], shift_s[MIP], b1s[MIP];

    const int tid = threadIdx.x;
    const int blk = blockIdx.x;           // n*4 + g
    const int n = blk >> 2, g = blk & 3;

    // ---- prologue: everything independent of pool's output ----
    for (int i = tid; i < MIP * CG; i += 128) {
        W1s[i] = W1[i];
        Whs[i] = Wh[i];
        Wws[i] = Ww[i];
    }
    bhs[tid] = bh[tid];
    bws[tid] = bw[tid];
    if (tid < MIP) {
        float sc = gamma[tid] * rsqrtf(var_[tid] + EPS_);
        scale_s[tid] = sc;
        shift_s[tid] = beta[tid] - mean_[tid] * sc;
        b1s[tid] = b1[tid];
    }
    __syncthreads();

    cudaGridDependencySynchronize();      // wait for pool's g_gh/g_gw

    const int l = tid;
    const float* __restrict__ src = (l < 64)
        ? &g_gh[((size_t)n * C_ + g * CG) * 64 + l]
        : &g_gw[((size_t)n * C_ + g * CG) * 64 + (l - 64)];

    float acc[MIP];
#pragma unroll
    for (int m = 0; m < MIP; m++) acc[m] = 0.f;
#pragma unroll 4
    for (int c = 0; c < CG; c++) {
        float yc = src[c * 64];
#pragma unroll
        for (int m = 0; m < MIP; m++) acc[m] += W1s[m * CG + c] * yc;
    }
#pragma unroll
    for (int m = 0; m < MIP; m++) {
        float v = acc[m] + b1s[m];
        v = v * scale_s[m] + shift_s[m];
        float r = fminf(fmaxf(v + 3.f, 0.f), 6.f);
        ys[m * 128 + l] = v * r * (1.f / 6.f);
    }
    __syncthreads();

    const int c = tid;
    float whr[MIP], wwr[MIP];
#pragma unroll
    for (int m = 0; m < MIP; m++) {
        whr[m] = Whs[c * MIP + m];
        wwr[m] = Wws[c * MIP + m];
    }
    const float bhc = bhs[c], bwc = bws[c];
    const int ch = g * CG + c;
    float* __restrict__ ah_out = &g_ah[((size_t)n * C_ + ch) * 64];
    float* __restrict__ aw_out = &g_aw[((size_t)n * C_ + ch) * 64];

#pragma unroll 2
    for (int l2 = 0; l2 < 64; l2++) {
        float sh = bhc, sw2 = bwc;
#pragma unroll
        for (int m = 0; m < MIP; m++) {
            sh  += whr[m] * ys[m * 128 + l2];
            sw2 += wwr[m] * ys[m * 128 + l2 + 64];
        }
        ah_out[l2] = 1.f / (1.f + __expf(-sh));
        aw_out[l2] = 1.f / (1.f + __expf(-sw2));
    }
}

// ---------------------------------------------------------------------------
// Kernel 3: apply (R9 proven shape, reversed). PDL: x loads precede the sync.
// ---------------------------------------------------------------------------
__global__ __launch_bounds__(256) void apply_kernel(const float* __restrict__ x,
                                                    float* __restrict__ out) {
    __shared__ float sa[64], sw[64];
    const int img = (N_ * C_ - 1) - blockIdx.x;   // reversed traversal
    const int n = img >> 9, ch = img & 511;
    const int tid = threadIdx.x;

    // ---- prologue: x reads are independent of mlp's gates ----
    const float4* __restrict__ xp = (const float4*)(x + (size_t)img * 4096);
    float4 v0 = xp[tid];
    float4 v1 = xp[256 + tid];
    float4 v2 = xp[512 + tid];
    float4 v3 = xp[768 + tid];

    cudaGridDependencySynchronize();      // wait for mlp's gates

    if (tid < 64)       sa[tid]      = g_ah[(size_t)img * 64 + tid];
    else if (tid < 128) sw[tid - 64] = g_aw[(size_t)img * 64 + (tid - 64)];
    __syncthreads();

    const int fc = (ch & 3) * 128 + (ch >> 2);
    float4* __restrict__ op = (float4*)(out + ((size_t)n * 512 + fc) * 4096);

    const int hb = tid >> 4;               // geometry: h = k*16 + tid/16
    const int w  = (tid & 15) << 2;        // w-quad (k-invariant)
    const float a0 = sa[hb], a1 = sa[hb + 16], a2 = sa[hb + 32], a3 = sa[hb + 48];
    const float w0 = sw[w], w1 = sw[w + 1], w2 = sw[w + 2], w3 = sw[w + 3];

    v0.x *= a0 * w0; v0.y *= a0 * w1; v0.z *= a0 * w2; v0.w *= a0 * w3;
    v1.x *= a1 * w0; v1.y *= a1 * w1; v1.z *= a1 * w2; v1.w *= a1 * w3;
    v2.x *= a2 * w0; v2.y *= a2 * w1; v2.z *= a2 * w2; v2.w *= a2 * w3;
    v3.x *= a3 * w0; v3.y *= a3 * w1; v3.z *= a3 * w2; v3.w *= a3 * w3;

    op[tid]       = v0;
    op[256 + tid] = v1;
    op[512 + tid] = v2;
    op[768 + tid] = v3;
}

extern "C" void kernel_launch(void* const* d_in, const int* in_sizes, int n_in,
                              void* d_out, int out_size) {
    const float* x     = (const float*)d_in[0];
    const float* W1    = (const float*)d_in[1];
    const float* b1    = (const float*)d_in[2];
    const float* gamma = (const float*)d_in[3];
    const float* beta  = (const float*)d_in[4];
    const float* mean_ = (const float*)d_in[5];
    const float* var_  = (const float*)d_in[6];
    const float* Wh    = (const float*)d_in[7];
    const float* bh    = (const float*)d_in[8];
    const float* Ww    = (const float*)d_in[9];
    const float* bw    = (const float*)d_in[10];
    float* out = (float*)d_out;

    // pool: plain launch
    pool_kernel<<<(N_ * C_) / 2, 256>>>(x);

    // mlp + apply: programmatic dependent launch (prologue overlap)
    cudaLaunchAttribute pdl[1];
    pdl[0].id = cudaLaunchAttributeProgrammaticStreamSerialization;
    pdl[0].val.programmaticStreamSerializationAllowed = 1;

    {
        cudaLaunchConfig_t cfg = {};
        cfg.gridDim = dim3(N_ * GRP, 1, 1);
        cfg.blockDim = dim3(128, 1, 1);
        cfg.attrs = pdl; cfg.numAttrs = 1; cfg.stream = 0;
        cudaLaunchKernelEx(&cfg, mlp_kernel, W1, b1, gamma, beta,
                           mean_, var_, Wh, bh, Ww, bw);
    }
    {
        cudaLaunchConfig_t cfg = {};
        cfg.gridDim = dim3(N_ * C_, 1, 1);
        cfg.blockDim = dim3(256, 1, 1);
        cfg.attrs = pdl; cfg.numAttrs = 1; cfg.stream = 0;
        cudaLaunchKernelEx(&cfg, apply_kernel, x, out);
    }
}